// round 3
// baseline (speedup 1.0000x reference)
#include <cuda_runtime.h>
#include <math.h>
#include <stdint.h>

// ---------------------------------------------------------------------------
// VectorQuantizerEMA  (N=32768 tokens, K=8192 codes, D=512)
// Outputs (flat f32): quantized_st[N*D], loss[1], perplexity[1],
//                     new_embedding[K*D], new_cs[K], new_ema_w[K*D]
// ---------------------------------------------------------------------------

#define NTOK 32768
#define KCODE 8192
#define DDIM 512

#define DECAY 0.99f
#define ONE_MINUS_DECAY 0.01f
#define EPS 1e-5f
#define COMMIT 0.25f

// output offsets (note: OE and OW are == 2 (mod 4) floats -> only 8B aligned!)
#define OQ  ((size_t)0)
#define OL  ((size_t)(NTOK) * DDIM)                 // 16777216
#define OP  (OL + 1)
#define OE  (OP + 1)                                // new_embedding
#define OC  (OE + (size_t)KCODE * DDIM)             // new_cs
#define OW  (OC + KCODE)                            // new_ema_w

// scratch (device globals: no allocation allowed)
__device__ float  g_halfE2[KCODE];
__device__ int    g_idx[NTOK];
__device__ float  g_cs[KCODE];
__device__ float  g_newcs[KCODE];
__device__ float  g_dw[(size_t)KCODE * DDIM];
__device__ double g_loss;

// ---------------------------------------------------------------------------
// f32x2 packed helpers (FFMA2 path — 2x fp32 FMA throughput on sm_103a)
// ---------------------------------------------------------------------------
__device__ __forceinline__ unsigned long long pack_dup(float a) {
    unsigned long long r;
    unsigned int u = __float_as_uint(a);
    asm("mov.b64 %0, {%1, %1};" : "=l"(r) : "r"(u));
    return r;
}
__device__ __forceinline__ unsigned long long pack2(float x, float y) {
    unsigned long long r;
    asm("mov.b64 %0, {%1, %2};" : "=l"(r) : "r"(__float_as_uint(x)), "r"(__float_as_uint(y)));
    return r;
}
__device__ __forceinline__ void ffma2(unsigned long long& d,
                                      unsigned long long a,
                                      unsigned long long b) {
    asm("fma.rn.f32x2 %0, %1, %2, %0;" : "+l"(d) : "l"(a), "l"(b));
}
__device__ __forceinline__ void unpack2(unsigned long long v, float& x, float& y) {
    unsigned int lo, hi;
    asm("mov.b64 {%0, %1}, %2;" : "=r"(lo), "=r"(hi) : "l"(v));
    x = __uint_as_float(lo);
    y = __uint_as_float(hi);
}

// ---------------------------------------------------------------------------
// K0: per-code half-norms + zero scratch
// grid = KCODE blocks, 256 threads
// ---------------------------------------------------------------------------
__global__ void k_prep(const float* __restrict__ E) {
    int k = blockIdx.x;
    int t = threadIdx.x;
    const float* row = E + (size_t)k * DDIM;
    float e0 = row[t], e1 = row[t + 256];
    float s = e0 * e0 + e1 * e1;

    // block reduce (256 threads)
    __shared__ float sh[8];
    int lane = t & 31, w = t >> 5;
    #pragma unroll
    for (int o = 16; o; o >>= 1) s += __shfl_down_sync(0xffffffffu, s, o);
    if (lane == 0) sh[w] = s;
    __syncthreads();
    if (w == 0) {
        float v = (lane < 8) ? sh[lane] : 0.f;
        #pragma unroll
        for (int o = 4; o; o >>= 1) v += __shfl_down_sync(0xffffffffu, v, o);
        if (lane == 0) g_halfE2[k] = 0.5f * v;
    }
    // zero scratch
    float* dwr = g_dw + (size_t)k * DDIM;
    dwr[t] = 0.f;
    dwr[t + 256] = 0.f;
    if (t == 0) g_cs[k] = 0.f;
    if (k == 0 && t == 0) g_loss = 0.0;
}

// ---------------------------------------------------------------------------
// K1: fused GEMM-argmax.  score[n][k] = x_n . e_k - 0.5*|e_k|^2, take argmax.
// BM=128 rows per block, loops all K in BN=128 col tiles, BK=32.
// 256 threads (16x16), 8x8 microtile, f32x2 packed FMA.
// grid = NTOK/128 = 256 blocks
// ---------------------------------------------------------------------------
#define BM 128
#define BN 128
#define BK 32
#define ASTRIDE 132  // BM + 4 pad: conflict-free transposed stores

__global__ __launch_bounds__(256, 1)
void k_argmax(const float* __restrict__ X, const float* __restrict__ E) {
    __shared__ float sm[2 * BK * ASTRIDE];   // 33792 B
    float* As = sm;                // [BK][ASTRIDE]
    float* Bs = sm + BK * ASTRIDE;

    const int tid = threadIdx.x;
    const int tx = tid & 15;   // col group 0..15
    const int ty = tid >> 4;   // row group 0..15
    const int m0 = blockIdx.x * BM;

    float bestv[8];
    int   besti[8];
    #pragma unroll
    for (int i = 0; i < 8; i++) { bestv[i] = -3.0e38f; besti[i] = 0; }

    for (int ct = 0; ct < KCODE / BN; ++ct) {
        const int c0 = ct * BN;

        // init acc = -halfE2 (folds the |e|^2 term into the GEMM)
        unsigned long long acc[8][4];
        #pragma unroll
        for (int jp = 0; jp < 4; jp++) {
            float2 h = *(const float2*)(&g_halfE2[c0 + tx * 8 + jp * 2]);
            unsigned long long hp = pack2(-h.x, -h.y);
            #pragma unroll
            for (int i = 0; i < 8; i++) acc[i][jp] = hp;
        }

        for (int kt = 0; kt < DDIM / BK; ++kt) {
            __syncthreads();  // protect previous iter's smem reads
            #pragma unroll
            for (int l = 0; l < 4; l++) {
                int ix = tid + l * 256;        // 0..1023
                int r  = ix >> 3;              // 0..127
                int c4 = ix & 7;               // float4 index in BK
                float4 v = *(const float4*)(X + (size_t)(m0 + r) * DDIM + kt * BK + c4 * 4);
                As[(c4 * 4 + 0) * ASTRIDE + r] = v.x;
                As[(c4 * 4 + 1) * ASTRIDE + r] = v.y;
                As[(c4 * 4 + 2) * ASTRIDE + r] = v.z;
                As[(c4 * 4 + 3) * ASTRIDE + r] = v.w;
                float4 w = *(const float4*)(E + (size_t)(c0 + r) * DDIM + kt * BK + c4 * 4);
                Bs[(c4 * 4 + 0) * ASTRIDE + r] = w.x;
                Bs[(c4 * 4 + 1) * ASTRIDE + r] = w.y;
                Bs[(c4 * 4 + 2) * ASTRIDE + r] = w.z;
                Bs[(c4 * 4 + 3) * ASTRIDE + r] = w.w;
            }
            __syncthreads();

            #pragma unroll 8
            for (int k = 0; k < BK; k++) {
                const float* Ar = As + k * ASTRIDE + ty * 8;
                float4 a0 = *(const float4*)Ar;
                float4 a1 = *(const float4*)(Ar + 4);
                unsigned long long ad[8];
                ad[0] = pack_dup(a0.x); ad[1] = pack_dup(a0.y);
                ad[2] = pack_dup(a0.z); ad[3] = pack_dup(a0.w);
                ad[4] = pack_dup(a1.x); ad[5] = pack_dup(a1.y);
                ad[6] = pack_dup(a1.z); ad[7] = pack_dup(a1.w);

                const float* Br = Bs + k * ASTRIDE + tx * 8;
                float4 b0 = *(const float4*)Br;
                float4 b1 = *(const float4*)(Br + 4);
                unsigned long long bp[4];
                bp[0] = pack2(b0.x, b0.y);
                bp[1] = pack2(b0.z, b0.w);
                bp[2] = pack2(b1.x, b1.y);
                bp[3] = pack2(b1.z, b1.w);

                #pragma unroll
                for (int i = 0; i < 8; i++) {
                    #pragma unroll
                    for (int jp = 0; jp < 4; jp++) ffma2(acc[i][jp], ad[i], bp[jp]);
                }
            }
        }

        // per-tile argmax update (ascending col order -> first-index tie rule)
        #pragma unroll
        for (int i = 0; i < 8; i++) {
            #pragma unroll
            for (int jp = 0; jp < 4; jp++) {
                float lo, hi;
                unpack2(acc[i][jp], lo, hi);
                int col = c0 + tx * 8 + jp * 2;
                if (lo > bestv[i]) { bestv[i] = lo; besti[i] = col; }
                if (hi > bestv[i]) { bestv[i] = hi; besti[i] = col + 1; }
            }
        }
    }

    // cross-thread reduce (16 col-groups per row) — reuse smem
    __syncthreads();
    float* sv = sm;                   // [128][16]
    int*   si = (int*)(sm + 2048);    // [128][16]
    #pragma unroll
    for (int i = 0; i < 8; i++) {
        int row = ty * 8 + i;
        sv[row * 16 + tx] = bestv[i];
        si[row * 16 + tx] = besti[i];
    }
    __syncthreads();
    if (tid < 128) {
        float bv = sv[tid * 16];
        int   bi = si[tid * 16];
        #pragma unroll
        for (int t = 1; t < 16; t++) {
            float v = sv[tid * 16 + t];
            int   ii = si[tid * 16 + t];
            if (v > bv || (v == bv && ii < bi)) { bv = v; bi = ii; }
        }
        g_idx[m0 + tid] = bi;
    }
}

// ---------------------------------------------------------------------------
// K2: gather quantized rows, write quantized_st = x + (q - x),
//     accumulate loss (double), scatter cluster_size & dw via atomics.
// grid = NTOK blocks, 128 threads
// ---------------------------------------------------------------------------
__global__ void k_scatter(const float* __restrict__ X, const float* __restrict__ E,
                          float* __restrict__ out) {
    int n = blockIdx.x;
    int k = g_idx[n];
    int t = threadIdx.x;

    float4 x = *(const float4*)(X + (size_t)n * DDIM + t * 4);
    float4 q = *(const float4*)(E + (size_t)k * DDIM + t * 4);
    float dx = q.x - x.x, dy = q.y - x.y, dz = q.z - x.z, dw = q.w - x.w;
    float4 o;
    o.x = x.x + dx; o.y = x.y + dy; o.z = x.z + dz; o.w = x.w + dw;
    *(float4*)(out + OQ + (size_t)n * DDIM + t * 4) = o;

    float ls = dx * dx + dy * dy + dz * dz + dw * dw;
    __shared__ float sh[4];
    int lane = t & 31, w = t >> 5;
    #pragma unroll
    for (int oo = 16; oo; oo >>= 1) ls += __shfl_down_sync(0xffffffffu, ls, oo);
    if (lane == 0) sh[w] = ls;
    __syncthreads();
    if (t == 0) {
        float s = sh[0] + sh[1] + sh[2] + sh[3];
        atomicAdd(&g_loss, (double)s);
        atomicAdd(&g_cs[k], 1.0f);
    }

    float* dwr = g_dw + (size_t)k * DDIM + t * 4;
    atomicAdd(dwr + 0, x.x);
    atomicAdd(dwr + 1, x.y);
    atomicAdd(dwr + 2, x.z);
    atomicAdd(dwr + 3, x.w);
}

// ---------------------------------------------------------------------------
// K3: single block: n_total, new_cs, loss, perplexity
// 1024 threads, each handles 8 codes
// ---------------------------------------------------------------------------
__global__ __launch_bounds__(1024, 1)
void k_stats(const float* __restrict__ ema_cs, float* __restrict__ out) {
    int t = threadIdx.x;
    float pre[8];
    double s_pre = 0.0, s_ent = 0.0;
    #pragma unroll
    for (int i = 0; i < 8; i++) {
        int k = t + i * 1024;
        float cs = g_cs[k];
        pre[i] = ema_cs[k] * DECAY + ONE_MINUS_DECAY * cs;
        s_pre += (double)pre[i];
        float p = cs * (1.0f / (float)NTOK);
        s_ent += (double)(p * logf(p + 1e-10f));
    }

    __shared__ double shp[32], she[32];
    int lane = t & 31, w = t >> 5;
    #pragma unroll
    for (int o = 16; o; o >>= 1) {
        s_pre += __shfl_down_sync(0xffffffffu, s_pre, o);
        s_ent += __shfl_down_sync(0xffffffffu, s_ent, o);
    }
    if (lane == 0) { shp[w] = s_pre; she[w] = s_ent; }
    __syncthreads();
    __shared__ double tot_pre_s, tot_ent_s;
    if (w == 0) {
        double vp = shp[lane], ve = she[lane];
        #pragma unroll
        for (int o = 16; o; o >>= 1) {
            vp += __shfl_down_sync(0xffffffffu, vp, o);
            ve += __shfl_down_sync(0xffffffffu, ve, o);
        }
        if (lane == 0) { tot_pre_s = vp; tot_ent_s = ve; }
    }
    __syncthreads();

    float ntot = (float)tot_pre_s;
    float denom = ntot + (float)KCODE * EPS;
    #pragma unroll
    for (int i = 0; i < 8; i++) {
        int k = t + i * 1024;
        float ncs = (pre[i] + EPS) / denom * ntot;
        g_newcs[k] = ncs;
        out[OC + k] = ncs;
    }
    if (t == 0) {
        out[OL] = (float)(COMMIT * g_loss / ((double)NTOK * (double)DDIM));
        out[OP] = (float)exp(-tot_ent_s);
    }
}

// ---------------------------------------------------------------------------
// K4: new_ema_w = ema_w*decay + (1-decay)*dw ;  new_embedding = new_ema_w/new_cs
// float2 accesses: out+OE / out+OW are only 8-byte aligned (offset == 2 mod 4).
// grid over K*D/2 float2 elements
// ---------------------------------------------------------------------------
__global__ void k_ema(const float* __restrict__ ema_w, float* __restrict__ out) {
    size_t gi = (size_t)blockIdx.x * blockDim.x + threadIdx.x;  // float2 index
    int k = (int)(gi >> 8);  // 256 float2 per row
    float ncs = g_newcs[k];
    float2 w = *(const float2*)(ema_w + gi * 2);
    float2 d = *(const float2*)(g_dw + gi * 2);
    float2 ew;
    ew.x = w.x * DECAY + ONE_MINUS_DECAY * d.x;
    ew.y = w.y * DECAY + ONE_MINUS_DECAY * d.y;
    *(float2*)(out + OW + gi * 2) = ew;
    float2 eb;
    eb.x = ew.x / ncs; eb.y = ew.y / ncs;
    *(float2*)(out + OE + gi * 2) = eb;
}

// ---------------------------------------------------------------------------
extern "C" void kernel_launch(void* const* d_in, const int* in_sizes, int n_in,
                              void* d_out, int out_size) {
    const float* X   = (const float*)d_in[0];  // inputs [N,D]
    const float* E   = (const float*)d_in[1];  // embedding [K,D]
    const float* ECS = (const float*)d_in[2];  // ema_cluster_size [K]
    const float* EW  = (const float*)d_in[3];  // ema_w [K,D]
    float* out = (float*)d_out;

    k_prep<<<KCODE, 256>>>(E);
    k_argmax<<<NTOK / BM, 256>>>(X, E);
    k_scatter<<<NTOK, 128>>>(X, E, out);
    k_stats<<<1, 1024>>>(ECS, out);
    k_ema<<<(KCODE * DDIM / 2) / 256, 256>>>(EW, out);
}

// round 5
// speedup vs baseline: 2.2400x; 2.2400x over previous
#include <cuda_runtime.h>
#include <cuda_bf16.h>
#include <math.h>
#include <stdint.h>

// ---------------------------------------------------------------------------
// VectorQuantizerEMA  (N=32768, K=8192, D=512) — mma.sync bf16 split version
// (tcgen05 unavailable: harness emits compute_103 PTX, no 'a' target)
// ---------------------------------------------------------------------------
#define NTOK 32768
#define KCODE 8192
#define DDIM 512

#define DECAY 0.99f
#define ONE_MINUS_DECAY 0.01f
#define EPS 1e-5f
#define COMMIT 0.25f

#define OQ  ((size_t)0)
#define OL  ((size_t)(NTOK) * DDIM)
#define OP  (OL + 1)
#define OE  (OP + 1)
#define OC  (OE + (size_t)KCODE * DDIM)
#define OW  (OC + KCODE)

// ------------------------- device scratch (no alloc) -----------------------
__device__ float          g_halfE2[KCODE];
__device__ int            g_idx[NTOK];
__device__ float          g_cs[KCODE];
__device__ float          g_newcs[KCODE];
__device__ float          g_dw[(size_t)KCODE * DDIM];
__device__ double         g_loss;
__device__ __nv_bfloat16  g_xhi[(size_t)NTOK * DDIM];
__device__ __nv_bfloat16  g_xlo[(size_t)NTOK * DDIM];
__device__ __nv_bfloat16  g_ehi[(size_t)KCODE * DDIM];
__device__ __nv_bfloat16  g_elo[(size_t)KCODE * DDIM];
__device__ float          g_bv[NTOK];
__device__ float          g_sv[NTOK];
__device__ int            g_bi[NTOK];
__device__ int            g_si[NTOK];

// ------------------------- helpers -----------------------------------------
__device__ __forceinline__ uint32_t smem_u32(const void* p) {
    uint32_t a;
    asm("{ .reg .u64 t; cvta.to.shared.u64 t, %1; cvt.u32.u64 %0, t; }" : "=r"(a) : "l"(p));
    return a;
}
__device__ __forceinline__ void cp16(uint32_t dst, const void* src) {
    asm volatile("cp.async.cg.shared.global [%0], [%1], 16;" :: "r"(dst), "l"(src));
}
#define CP_COMMIT() asm volatile("cp.async.commit_group;" ::: "memory")

__device__ __forceinline__ void ldm_x4(uint32_t addr, uint32_t& r0, uint32_t& r1,
                                       uint32_t& r2, uint32_t& r3) {
    asm volatile("ldmatrix.sync.aligned.m8n8.x4.shared.b16 {%0,%1,%2,%3}, [%4];"
                 : "=r"(r0), "=r"(r1), "=r"(r2), "=r"(r3) : "r"(addr));
}
__device__ __forceinline__ void mma16816(float* d, const uint32_t* a, const uint32_t* b) {
    asm volatile("mma.sync.aligned.m16n8k16.row.col.f32.bf16.bf16.f32 "
                 "{%0,%1,%2,%3}, {%4,%5,%6,%7}, {%8,%9}, {%0,%1,%2,%3};"
                 : "+f"(d[0]), "+f"(d[1]), "+f"(d[2]), "+f"(d[3])
                 : "r"(a[0]), "r"(a[1]), "r"(a[2]), "r"(a[3]), "r"(b[0]), "r"(b[1]));
}
// merge sorted top2 (t) with sorted top2 (o)
__device__ __forceinline__ void merge2(float& t1v, int& t1i, float& t2v, int& t2i,
                                       float o1v, int o1i, float o2v, int o2i) {
    if (o1v > t1v) {
        float n2v = t1v; int n2i = t1i;
        if (o2v > n2v) { n2v = o2v; n2i = o2i; }
        t1v = o1v; t1i = o1i; t2v = n2v; t2i = n2i;
    } else if (o1v > t2v) {
        t2v = o1v; t2i = o1i;
    }
}

// ---------------------------------------------------------------------------
// K0a: per-code half-norms, E bf16 hi/lo split, zero scratch
// ---------------------------------------------------------------------------
__global__ void k_prep(const float* __restrict__ E) {
    int k = blockIdx.x;
    int t = threadIdx.x;
    const float* row = E + (size_t)k * DDIM;
    float e0 = row[t], e1 = row[t + 256];

    __nv_bfloat16 h0 = __float2bfloat16_rn(e0);
    __nv_bfloat16 h1 = __float2bfloat16_rn(e1);
    g_ehi[(size_t)k * DDIM + t]       = h0;
    g_ehi[(size_t)k * DDIM + t + 256] = h1;
    g_elo[(size_t)k * DDIM + t]       = __float2bfloat16_rn(e0 - __bfloat162float(h0));
    g_elo[(size_t)k * DDIM + t + 256] = __float2bfloat16_rn(e1 - __bfloat162float(h1));

    float s = e0 * e0 + e1 * e1;
    __shared__ float sh[8];
    int lane = t & 31, w = t >> 5;
    #pragma unroll
    for (int o = 16; o; o >>= 1) s += __shfl_down_sync(0xffffffffu, s, o);
    if (lane == 0) sh[w] = s;
    __syncthreads();
    if (w == 0) {
        float v = (lane < 8) ? sh[lane] : 0.f;
        #pragma unroll
        for (int o = 4; o; o >>= 1) v += __shfl_down_sync(0xffffffffu, v, o);
        if (lane == 0) g_halfE2[k] = 0.5f * v;
    }
    float* dwr = g_dw + (size_t)k * DDIM;
    dwr[t] = 0.f;
    dwr[t + 256] = 0.f;
    if (t == 0) g_cs[k] = 0.f;
    if (k == 0 && t == 0) g_loss = 0.0;
}

// K0b: X bf16 hi/lo split
__global__ void k_cvtx(const float* __restrict__ X) {
    size_t i = (size_t)blockIdx.x * 256 + threadIdx.x;
    float x = X[i];
    __nv_bfloat16 h = __float2bfloat16_rn(x);
    g_xhi[i] = h;
    g_xlo[i] = __float2bfloat16_rn(x - __bfloat162float(h));
}

// ---------------------------------------------------------------------------
// K1: fused mma.sync GEMM + top-2 argmax.
// CTA: 128 tokens, sweeps 64 code tiles of 128. Contraction (virtual 1536):
//   kc 0-15: Xhi.Ehi, 16-31: Xhi.Elo, 32-47: Xlo.Ehi   (BK=32)
// acc init = -halfE2[col]. 3-stage cp.async pipeline. 8 warps (4x2), 32x64.
// ---------------------------------------------------------------------------
#define BM 128
#define BN 128
#define BK 32
#define KCH 48                       // chunks per col tile
#define NTILE (KCODE / BN)           // 64
#define GTOT (NTILE * KCH)           // 3072
#define SROW 40                      // bf16 stride (32 + 8 pad) = 80 B
#define STAGE_A (BM * SROW * 2)      // 10240 B
#define STAGE_SZ (2 * STAGE_A)       // 20480 B (A then B)
#define GEMM_SMEM (3 * STAGE_SZ)     // 61440 B

__device__ __forceinline__ void load_chunk(int g, int m0, uint32_t sb, int tid) {
    const int ct = g / KCH, kc = g % KCH;
    const int n0 = ct * BN;
    const int sel = kc >> 4;                       // 0,1,2
    const int koff = (kc & 15) * BK;               // element offset in D
    const __nv_bfloat16* Asrc = (sel == 2) ? g_xlo : g_xhi;
    const __nv_bfloat16* Bsrc = (sel == 1) ? g_elo : g_ehi;
    const uint32_t stA = sb + (g % 3) * STAGE_SZ;
    const uint32_t stB = stA + STAGE_A;
    #pragma unroll
    for (int i = 0; i < 2; i++) {
        int idx = tid + i * 256;                   // 0..511
        int row = idx >> 2, c = idx & 3;
        cp16(stA + row * (SROW * 2) + c * 16,
             Asrc + (size_t)(m0 + row) * DDIM + koff + c * 8);
        cp16(stB + row * (SROW * 2) + c * 16,
             Bsrc + (size_t)(n0 + row) * DDIM + koff + c * 8);
    }
    CP_COMMIT();
}

__global__ __launch_bounds__(256, 2)
void k_gemm() {
    extern __shared__ char smem[];
    const uint32_t sb = smem_u32(smem);
    const int tid = threadIdx.x;
    const int wid = tid >> 5;
    const int lane = tid & 31;
    const int wm = wid >> 1;          // 0..3  (rows wm*32)
    const int wn = wid & 1;           // 0..1  (cols wn*64)
    const int m0 = blockIdx.x * BM;

    float acc[2][8][4];
    float t1v[4], t2v[4];
    int   t1i[4], t2i[4];
    #pragma unroll
    for (int s = 0; s < 4; s++) { t1v[s] = -3.0e38f; t2v[s] = -3.0e38f; t1i[s] = 0; t2i[s] = 0; }

    // precomputed ldmatrix lane addressing (byte offsets within stage)
    const uint32_t a_off = (uint32_t)(wm * 32 + (lane & 15)) * (SROW * 2) + (lane >> 4) * 16;
    const uint32_t b_row = (uint32_t)(wn * 64 + (lane & 7) + ((lane >> 4) << 3));
    const uint32_t b_off = b_row * (SROW * 2) + ((lane >> 3) & 1) * 16;

    load_chunk(0, m0, sb, tid);
    load_chunk(1, m0, sb, tid);
    load_chunk(2, m0, sb, tid);

    for (int g = 0; g < GTOT; ++g) {
        const int ct = g / KCH, kc = g % KCH;

        if (kc == 0) {
            const int n0 = ct * BN;
            #pragma unroll
            for (int nf = 0; nf < 8; nf++) {
                int col = n0 + wn * 64 + nf * 8 + (lane & 3) * 2;
                float2 h = *(const float2*)(&g_halfE2[col]);
                acc[0][nf][0] = -h.x; acc[0][nf][1] = -h.y;
                acc[0][nf][2] = -h.x; acc[0][nf][3] = -h.y;
                acc[1][nf][0] = -h.x; acc[1][nf][1] = -h.y;
                acc[1][nf][2] = -h.x; acc[1][nf][3] = -h.y;
            }
        }

        asm volatile("cp.async.wait_group 2;" ::: "memory");
        __syncthreads();

        const uint32_t stA = sb + (g % 3) * STAGE_SZ;
        const uint32_t stB = stA + STAGE_A;
        #pragma unroll
        for (int ks = 0; ks < 2; ks++) {
            uint32_t a[2][4];
            ldm_x4(stA + a_off + ks * 32 + 0 * (16 * SROW * 2) + (wm * 0),
                   a[0][0], a[0][1], a[0][2], a[0][3]);
            ldm_x4(stA + a_off + ks * 32 + 16 * (SROW * 2),
                   a[1][0], a[1][1], a[1][2], a[1][3]);
            uint32_t b[8][2];
            #pragma unroll
            for (int np = 0; np < 4; np++) {
                uint32_t r0, r1, r2, r3;
                ldm_x4(stB + b_off + ks * 32 + np * (16 * SROW * 2), r0, r1, r2, r3);
                b[np * 2][0] = r0; b[np * 2][1] = r1;
                b[np * 2 + 1][0] = r2; b[np * 2 + 1][1] = r3;
            }
            #pragma unroll
            for (int mf = 0; mf < 2; mf++)
                #pragma unroll
                for (int nf = 0; nf < 8; nf++)
                    mma16816(acc[mf][nf], a[mf], b[nf]);
        }
        __syncthreads();
        if (g + 3 < GTOT) load_chunk(g + 3, m0, sb, tid);

        if (kc == KCH - 1) {
            const int n0 = ct * BN;
            #pragma unroll
            for (int mf = 0; mf < 2; mf++)
                #pragma unroll
                for (int h = 0; h < 2; h++) {
                    int s = mf * 2 + h;
                    #pragma unroll
                    for (int nf = 0; nf < 8; nf++) {
                        int colb = n0 + wn * 64 + nf * 8 + (lane & 3) * 2;
                        float v0 = acc[mf][nf][h * 2 + 0];
                        float v1 = acc[mf][nf][h * 2 + 1];
                        if (v0 > t1v[s]) { t2v[s] = t1v[s]; t2i[s] = t1i[s]; t1v[s] = v0; t1i[s] = colb; }
                        else if (v0 > t2v[s]) { t2v[s] = v0; t2i[s] = colb; }
                        if (v1 > t1v[s]) { t2v[s] = t1v[s]; t2i[s] = t1i[s]; t1v[s] = v1; t1i[s] = colb + 1; }
                        else if (v1 > t2v[s]) { t2v[s] = v1; t2i[s] = colb + 1; }
                    }
                }
        }
    }

    // warp-level reduce: lanes sharing a row differ in bits 0-1
    #pragma unroll
    for (int s = 0; s < 4; s++) {
        #pragma unroll
        for (int d = 1; d <= 2; d <<= 1) {
            float o1v = __shfl_xor_sync(0xffffffffu, t1v[s], d);
            int   o1i = __shfl_xor_sync(0xffffffffu, t1i[s], d);
            float o2v = __shfl_xor_sync(0xffffffffu, t2v[s], d);
            int   o2i = __shfl_xor_sync(0xffffffffu, t2i[s], d);
            merge2(t1v[s], t1i[s], t2v[s], t2i[s], o1v, o1i, o2v, o2i);
        }
    }

    // cross-warp (warp_n 0/1) reduce through smem (stages are dead now)
    __syncthreads();
    float* c_v = (float*)smem;            // [128][2][2]
    int*   c_i = (int*)(smem + 2048);     // [128][2][2]
    if ((lane & 3) == 0) {
        #pragma unroll
        for (int s = 0; s < 4; s++) {
            int mf = s >> 1, h = s & 1;
            int row = wm * 32 + mf * 16 + h * 8 + (lane >> 2);
            c_v[(row * 2 + wn) * 2 + 0] = t1v[s];
            c_v[(row * 2 + wn) * 2 + 1] = t2v[s];
            c_i[(row * 2 + wn) * 2 + 0] = t1i[s];
            c_i[(row * 2 + wn) * 2 + 1] = t2i[s];
        }
    }
    __syncthreads();
    if (tid < BM) {
        float v1 = c_v[(tid * 2) * 2 + 0], v2 = c_v[(tid * 2) * 2 + 1];
        int   i1 = c_i[(tid * 2) * 2 + 0], i2 = c_i[(tid * 2) * 2 + 1];
        merge2(v1, i1, v2, i2,
               c_v[(tid * 2 + 1) * 2 + 0], c_i[(tid * 2 + 1) * 2 + 0],
               c_v[(tid * 2 + 1) * 2 + 1], c_i[(tid * 2 + 1) * 2 + 1]);
        g_bv[m0 + tid] = v1; g_bi[m0 + tid] = i1;
        g_sv[m0 + tid] = v2; g_si[m0 + tid] = i2;
    }
}

// ---------------------------------------------------------------------------
// K1b: exact fp32 refine of approx top-2 (one warp per token)
// ---------------------------------------------------------------------------
__global__ void k_refine(const float* __restrict__ X, const float* __restrict__ E) {
    const int n = blockIdx.x * 8 + (threadIdx.x >> 5);
    const int lane = threadIdx.x & 31;
    const int bi = g_bi[n], si = g_si[n];
    const float* x  = X + (size_t)n * DDIM;
    const float* e1 = E + (size_t)bi * DDIM;
    const float* e2 = E + (size_t)si * DDIM;
    float s1 = 0.f, s2 = 0.f;
    #pragma unroll
    for (int i = 0; i < DDIM / 32; i++) {
        float xv = x[lane + i * 32];
        s1 = fmaf(xv, e1[lane + i * 32], s1);
        s2 = fmaf(xv, e2[lane + i * 32], s2);
    }
    #pragma unroll
    for (int o = 16; o; o >>= 1) {
        s1 += __shfl_xor_sync(0xffffffffu, s1, o);
        s2 += __shfl_xor_sync(0xffffffffu, s2, o);
    }
    if (lane == 0) {
        float sc1 = s1 - g_halfE2[bi];
        float sc2 = s2 - g_halfE2[si];
        int idx = bi;
        if (sc2 > sc1 || (sc2 == sc1 && si < bi)) idx = si;
        g_idx[n] = idx;
    }
}

// ---------------------------------------------------------------------------
// K2: gather + straight-through output, loss, scatter cs/dw
// ---------------------------------------------------------------------------
__global__ void k_scatter(const float* __restrict__ X, const float* __restrict__ E,
                          float* __restrict__ out) {
    int n = blockIdx.x;
    int k = g_idx[n];
    int t = threadIdx.x;

    float4 x = *(const float4*)(X + (size_t)n * DDIM + t * 4);
    float4 q = *(const float4*)(E + (size_t)k * DDIM + t * 4);
    float dx = q.x - x.x, dy = q.y - x.y, dz = q.z - x.z, dw = q.w - x.w;
    float4 o;
    o.x = x.x + dx; o.y = x.y + dy; o.z = x.z + dz; o.w = x.w + dw;
    *(float4*)(out + OQ + (size_t)n * DDIM + t * 4) = o;

    float ls = dx * dx + dy * dy + dz * dz + dw * dw;
    __shared__ float sh[4];
    int lane = t & 31, w = t >> 5;
    #pragma unroll
    for (int oo = 16; oo; oo >>= 1) ls += __shfl_down_sync(0xffffffffu, ls, oo);
    if (lane == 0) sh[w] = ls;
    __syncthreads();
    if (t == 0) {
        float s = sh[0] + sh[1] + sh[2] + sh[3];
        atomicAdd(&g_loss, (double)s);
        atomicAdd(&g_cs[k], 1.0f);
    }

    float* dwr = g_dw + (size_t)k * DDIM + t * 4;
    atomicAdd(dwr + 0, x.x);
    atomicAdd(dwr + 1, x.y);
    atomicAdd(dwr + 2, x.z);
    atomicAdd(dwr + 3, x.w);
}

// K3: stats
__global__ __launch_bounds__(1024, 1)
void k_stats(const float* __restrict__ ema_cs, float* __restrict__ out) {
    int t = threadIdx.x;
    float pre[8];
    double s_pre = 0.0, s_ent = 0.0;
    #pragma unroll
    for (int i = 0; i < 8; i++) {
        int k = t + i * 1024;
        float cs = g_cs[k];
        pre[i] = ema_cs[k] * DECAY + ONE_MINUS_DECAY * cs;
        s_pre += (double)pre[i];
        float p = cs * (1.0f / (float)NTOK);
        s_ent += (double)(p * logf(p + 1e-10f));
    }
    __shared__ double shp[32], she[32];
    int lane = t & 31, w = t >> 5;
    #pragma unroll
    for (int o = 16; o; o >>= 1) {
        s_pre += __shfl_down_sync(0xffffffffu, s_pre, o);
        s_ent += __shfl_down_sync(0xffffffffu, s_ent, o);
    }
    if (lane == 0) { shp[w] = s_pre; she[w] = s_ent; }
    __syncthreads();
    __shared__ double tot_pre_s, tot_ent_s;
    if (w == 0) {
        double vp = shp[lane], ve = she[lane];
        #pragma unroll
        for (int o = 16; o; o >>= 1) {
            vp += __shfl_down_sync(0xffffffffu, vp, o);
            ve += __shfl_down_sync(0xffffffffu, ve, o);
        }
        if (lane == 0) { tot_pre_s = vp; tot_ent_s = ve; }
    }
    __syncthreads();
    float ntot = (float)tot_pre_s;
    float denom = ntot + (float)KCODE * EPS;
    #pragma unroll
    for (int i = 0; i < 8; i++) {
        int k = t + i * 1024;
        float ncs = (pre[i] + EPS) / denom * ntot;
        g_newcs[k] = ncs;
        out[OC + k] = ncs;
    }
    if (t == 0) {
        out[OL] = (float)(COMMIT * g_loss / ((double)NTOK * (double)DDIM));
        out[OP] = (float)exp(-tot_ent_s);
    }
}

// K4: EMA updates (float2: OE/OW only 8B aligned)
__global__ void k_ema(const float* __restrict__ ema_w, float* __restrict__ out) {
    size_t gi = (size_t)blockIdx.x * blockDim.x + threadIdx.x;
    int k = (int)(gi >> 8);
    float ncs = g_newcs[k];
    float2 w = *(const float2*)(ema_w + gi * 2);
    float2 d = *(const float2*)(g_dw + gi * 2);
    float2 ew;
    ew.x = w.x * DECAY + ONE_MINUS_DECAY * d.x;
    ew.y = w.y * DECAY + ONE_MINUS_DECAY * d.y;
    *(float2*)(out + OW + gi * 2) = ew;
    float2 eb;
    eb.x = ew.x / ncs; eb.y = ew.y / ncs;
    *(float2*)(out + OE + gi * 2) = eb;
}

// ---------------------------------------------------------------------------
extern "C" void kernel_launch(void* const* d_in, const int* in_sizes, int n_in,
                              void* d_out, int out_size) {
    const float* X   = (const float*)d_in[0];
    const float* E   = (const float*)d_in[1];
    const float* ECS = (const float*)d_in[2];
    const float* EW  = (const float*)d_in[3];
    float* out = (float*)d_out;

    cudaFuncSetAttribute(k_gemm, cudaFuncAttributeMaxDynamicSharedMemorySize, GEMM_SMEM);

    k_prep<<<KCODE, 256>>>(E);
    k_cvtx<<<(NTOK * DDIM) / 256, 256>>>(X);
    k_gemm<<<NTOK / BM, 256, GEMM_SMEM>>>();
    k_refine<<<NTOK / 8, 256>>>(X, E);
    k_scatter<<<NTOK, 128>>>(X, E, out);
    k_stats<<<1, 1024>>>(ECS, out);
    k_ema<<<(KCODE * DDIM / 2) / 256, 256>>>(EW, out);
}